// round 6
// baseline (speedup 1.0000x reference)
#include <cuda_runtime.h>

#define Bb   8
#define HW   1024
#define Cc   512
#define C4   128
#define NBLK 128
#define NTHR 512
#define DYN_BYTES (64 * 1024 + 32 * 1024)   // wbuf 64KB + psum 32KB

// ---------------- sync counters, one per 128-B line ---------------------------
struct alignas(128) Line { unsigned v; unsigned pad[31]; };
__device__ Line cnt0[8];    // P1 arrivals per batch (16 each; sum=128)
__device__ Line cnt2[8];    // xr arrivals   (64, 8/line)
__device__ Line cnt3[8];    // ksum arrivals (64, 8/line)
__device__ Line cnt4[2];    // wpart arrivals (16, 8/line)
__device__ Line cnt6[1];    // upart arrivals (16)
__device__ Line cnt7[8];    // epilogue arrivals per batch (16 each)
__device__ Line cnt8[16];   // final ack (8/line)
__device__ unsigned g_mnk[Bb] = {0xFFFFFFFFu,0xFFFFFFFFu,0xFFFFFFFFu,0xFFFFFFFFu,
                                 0xFFFFFFFFu,0xFFFFFFFFu,0xFFFFFFFFu,0xFFFFFFFFu};
__device__ unsigned g_mxk[Bb] = {0,0,0,0,0,0,0,0};

// ---------------- data scratch (fully rewritten every launch) -----------------
__device__ __align__(16) float4 g_partial[Bb][16][C4];
__device__ __align__(16) float  g_xr[Bb][Cc];
__device__ __align__(16) float  g_ksum[Bb][Cc];
__device__ __align__(16) float  g_wpart[16][Bb][Cc];
__device__ __align__(16) float  g_w[Bb][Cc];
__device__ __align__(16) float  g_upart[16][Bb][Cc];

__device__ __forceinline__ unsigned ld_relaxed(const unsigned* p) {
    unsigned v;
    asm volatile("ld.relaxed.gpu.u32 %0, [%1];" : "=r"(v) : "l"(p) : "memory");
    return v;
}
__device__ __forceinline__ unsigned enc(float f) {
    unsigned u = __float_as_uint(f);
    return (u & 0x80000000u) ? ~u : (u | 0x80000000u);
}
__device__ __forceinline__ float dec(unsigned k) {
    return (k & 0x80000000u) ? __uint_as_float(k ^ 0x80000000u)
                             : __uint_as_float(~k);
}

#define ARRIVE_LINE(lineptr)                                          \
    do { __syncthreads();                                             \
         if (t == 0) { __threadfence(); atomicAdd(&(lineptr)->v, 1u); } \
    } while (0)
#define WAIT_LINES(arr, n, tgt)                                       \
    do { if (t == 0) {                                                \
             unsigned s_;                                             \
             do { s_ = 0;                                             \
                  _Pragma("unroll")                                   \
                  for (int i_ = 0; i_ < (n); ++i_) s_ += ld_relaxed(&(arr)[i_].v); \
             } while (s_ < (unsigned)(tgt));                          \
             __threadfence();                                         \
         }                                                            \
         __syncthreads();                                             \
    } while (0)

__global__ void __launch_bounds__(NTHR)
fused_kernel(const float* __restrict__ x,
             const float* __restrict__ conv_w, const float* __restrict__ conv_b,
             const float* __restrict__ q_w,
             const float* __restrict__ k_w,    const float* __restrict__ k_b,
             float* __restrict__ out)
{
    extern __shared__ float dynsh[];
    float*  wbuf  = dynsh;                                  // 16384 f (64 KB)
    float4* wbuf4 = reinterpret_cast<float4*>(dynsh);
    float*  psum  = dynsh + 16384;                          // 8192 f (32 KB)
    __shared__ __align__(16) float shA[Bb][Cc];             // 16 KB
    __shared__ __align__(16) float shB[Cc];                 // 2 KB
    __shared__ float s_part[16][Bb];
    __shared__ float shW[Bb][32];
    __shared__ float sdot[64];
    float4* shA4 = reinterpret_cast<float4*>(shA);

    const int g    = blockIdx.x;
    const int t    = threadIdx.x;
    const int warp = t >> 5, lane = t & 31;
    const int b_own = g >> 4, s_own = g & 15;
    const int c4t = t & 127, rs = t >> 7;

    // ============ P1: x tile -> registers (+colsum) & weight prefetch ========
    float4 xreg[16];
    {
        const float4* base = reinterpret_cast<const float4*>(x)
                           + ((size_t)(b_own * HW + s_own * 64 + rs * 16)) * C4 + c4t;
        float4 acc = make_float4(0.f, 0.f, 0.f, 0.f);
#pragma unroll
        for (int p = 0; p < 16; ++p) {
            xreg[p] = base[(size_t)p * C4];
            acc.x += xreg[p].x; acc.y += xreg[p].y;
            acc.z += xreg[p].z; acc.w += xreg[p].w;
        }
        shA4[rs * C4 + c4t] = acc;

        // weight prefetch (overlaps x loads)
        if (g >= 64) {                      // W: conv rows (g-64)*8 + k_w rows
            const float4* s1 = reinterpret_cast<const float4*>(conv_w) + (g - 64) * 1024;
            const float4* s2 = reinterpret_cast<const float4*>(k_w)    + (g - 64) * 1024;
#pragma unroll
            for (int i = 0; i < 2; ++i) wbuf4[t + i * NTHR]        = s1[t + i * NTHR];
#pragma unroll
            for (int i = 0; i < 2; ++i) wbuf4[1024 + t + i * NTHR] = s2[t + i * NTHR];
        } else if (g < 16) {                // C: q_w rows [g*32, +32)
            const float4* src = reinterpret_cast<const float4*>(q_w) + g * 4096;
#pragma unroll
            for (int i = 0; i < 8; ++i) wbuf4[t + i * NTHR] = src[t + i * NTHR];
        } else if (g < 32) {                // D: conv_w rows [(g-16)*32, +32)
            const float4* src = reinterpret_cast<const float4*>(conv_w) + (g - 16) * 4096;
#pragma unroll
            for (int i = 0; i < 8; ++i) wbuf4[t + i * NTHR] = src[t + i * NTHR];
        }
        __syncthreads();
        if (t < C4) {
            float4 a = shA4[t], p1 = shA4[C4 + t], p2 = shA4[2 * C4 + t], p3 = shA4[3 * C4 + t];
            a.x += p1.x + p2.x + p3.x;  a.y += p1.y + p2.y + p3.y;
            a.z += p1.z + p2.z + p3.z;  a.w += p1.w + p2.w + p3.w;
            g_partial[b_own][s_own][t] = a;
        }
    }
    ARRIVE_LINE(&cnt0[b_own]);

    // ============ W blocks (64..127): Xsum + xr matvec, then Ksum matvec =====
    if (g >= 64) {
        const int a = g - 64;               // 0..63, rows [a*8, a*8+8)
        WAIT_LINES(cnt0, 8, NBLK);
        // --- local full Xsum reduce into shA (redundant per block; no handoff)
#pragma unroll
        for (int i = 0; i < 2; ++i) {
            const int idx = t + i * NTHR;   // 0..1023 = b*128 + c4
            const int bb = idx >> 7, cc4 = idx & 127;
            float4 s = make_float4(0.f, 0.f, 0.f, 0.f);
#pragma unroll
            for (int sp = 0; sp < 16; ++sp) {
                float4 v = g_partial[bb][sp][cc4];
                s.x += v.x; s.y += v.y; s.z += v.z; s.w += v.w;
            }
            shA4[idx] = s;
        }
        __syncthreads();

        // --- xr matvec: 8 rows, 2 warps/row (halves of c)
        {
            const int rowL = warp >> 1, h = warp & 1;
            float acc[Bb];
#pragma unroll
            for (int b = 0; b < Bb; ++b) acc[b] = 0.f;
#pragma unroll
            for (int k = 0; k < 2; ++k) {
                const int c4 = h * 64 + k * 32 + lane;
                const float4 wv = wbuf4[rowL * C4 + c4];
#pragma unroll
                for (int b = 0; b < Bb; ++b) {
                    const float4 xa = shA4[b * C4 + c4];
                    acc[b] += wv.x * xa.x + wv.y * xa.y + wv.z * xa.z + wv.w * xa.w;
                }
            }
#pragma unroll
            for (int b = 0; b < Bb; ++b)
#pragma unroll
                for (int off = 16; off; off >>= 1)
                    acc[b] += __shfl_xor_sync(0xffffffffu, acc[b], off);
            if (lane == 0)
#pragma unroll
                for (int b = 0; b < Bb; ++b) s_part[warp][b] = acc[b];
        }
        __syncthreads();
        if (t < 64) {
            const int rowL = t >> 3, b = t & 7;
            const int o = a * 8 + rowL;
            const float v = s_part[rowL * 2][b] + s_part[rowL * 2 + 1][b]
                          + (float)HW * conv_b[o] + shA[b][o];
            g_xr[b][o] = v;
        }
        ARRIVE_LINE(&cnt2[a & 7]);
        WAIT_LINES(cnt2, 8, 64);

        // --- gather xr, Ksum matvec (same structure, k_w half of wbuf)
#pragma unroll
        for (int i = 0; i < 2; ++i)
            shA4[t + i * NTHR] = reinterpret_cast<const float4*>(g_xr)[t + i * NTHR];
        __syncthreads();
        {
            const int rowL = warp >> 1, h = warp & 1;
            float acc[Bb];
#pragma unroll
            for (int b = 0; b < Bb; ++b) acc[b] = 0.f;
#pragma unroll
            for (int k = 0; k < 2; ++k) {
                const int c4 = h * 64 + k * 32 + lane;
                const float4 wv = wbuf4[1024 + rowL * C4 + c4];
#pragma unroll
                for (int b = 0; b < Bb; ++b) {
                    const float4 xa = shA4[b * C4 + c4];
                    acc[b] += wv.x * xa.x + wv.y * xa.y + wv.z * xa.z + wv.w * xa.w;
                }
            }
#pragma unroll
            for (int b = 0; b < Bb; ++b)
#pragma unroll
                for (int off = 16; off; off >>= 1)
                    acc[b] += __shfl_xor_sync(0xffffffffu, acc[b], off);
            if (lane == 0)
#pragma unroll
                for (int b = 0; b < Bb; ++b) s_part[warp][b] = acc[b];
        }
        __syncthreads();
        if (t < 64) {
            const int rowL = t >> 3, b = t & 7;
            const int o = a * 8 + rowL;
            g_ksum[b][o] = s_part[rowL * 2][b] + s_part[rowL * 2 + 1][b]
                         + (float)HW * k_b[o];
        }
        ARRIVE_LINE(&cnt3[a & 7]);
    }

    // ============ C blocks (0..15): v + w partials ============================
    if (g < 16) {
        WAIT_LINES(cnt3, 8, 64);
#pragma unroll
        for (int i = 0; i < 2; ++i)
            shA4[t + i * NTHR] = reinterpret_cast<const float4*>(g_ksum)[t + i * NTHR];
        __syncthreads();
        float tot = 0.f;
#pragma unroll
        for (int b = 0; b < Bb; ++b) tot += shA[b][t];
        shB[t] = tot;
        __syncthreads();
#pragma unroll
        for (int b = 0; b < Bb; ++b) shA[b][t] = shB[t] - shA[b][t];   // v in place
        __syncthreads();

        float vreg[Bb];
#pragma unroll
        for (int b = 0; b < Bb; ++b) vreg[b] = shA[b][g * 32 + lane];
        float acc[Bb];
#pragma unroll
        for (int b = 0; b < Bb; ++b) acc[b] = 0.f;
#pragma unroll
        for (int oo = 0; oo < 32; ++oo) {
            const float wv = wbuf[oo * Cc + t];
#pragma unroll
            for (int b = 0; b < Bb; ++b)
                acc[b] += wv * __shfl_sync(0xffffffffu, vreg[b], oo);
        }
#pragma unroll
        for (int b = 0; b < Bb; ++b) g_wpart[g][b][t] = acc[b];
        ARRIVE_LINE(&cnt4[g & 1]);
    }

    // ============ D blocks (16..31): w reduce (own o-chunk) + u partials ======
    if (g >= 16 && g < 32) {
        const int j = g - 16;
        WAIT_LINES(cnt4, 2, 16);
        if (t < 256) {
            const int b = t >> 5, oo = t & 31;
            float s = 0.f;
#pragma unroll
            for (int jj = 0; jj < 16; ++jj) s += g_wpart[jj][b][j * 32 + oo];
            shW[b][oo] = s;
            g_w[b][j * 32 + oo] = s;       // also the +w residual for P6
        }
        __syncthreads();

        float vreg[Bb];
#pragma unroll
        for (int b = 0; b < Bb; ++b) vreg[b] = shW[b][lane];
        float acc[Bb];
#pragma unroll
        for (int b = 0; b < Bb; ++b) acc[b] = 0.f;
#pragma unroll
        for (int oo = 0; oo < 32; ++oo) {
            const float wv = wbuf[oo * Cc + t];
#pragma unroll
            for (int b = 0; b < Bb; ++b)
                acc[b] += wv * __shfl_sync(0xffffffffu, vreg[b], oo);
        }
#pragma unroll
        for (int b = 0; b < Bb; ++b) g_upart[j][b][t] = acc[b];
        ARRIVE_LINE(&cnt6[0]);
    }

    // ============ all blocks: u assemble + dot + epilogue =====================
    WAIT_LINES(cnt6, 1, 16);
    {
        float a = g_w[b_own][t];
#pragma unroll
        for (int jj = 0; jj < 16; ++jj) a += g_upart[jj][b_own][t];
        shB[t] = a;
        __syncthreads();

        const float4 uv = reinterpret_cast<const float4*>(shB)[c4t];
#pragma unroll
        for (int p = 0; p < 16; ++p) {
            const float4 xv = xreg[p];
            psum[(rs * 16 + p) * C4 + c4t] =
                xv.x * uv.x + xv.y * uv.y + xv.z * uv.z + xv.w * uv.w;
        }
        __syncthreads();
#pragma unroll
        for (int rr = 0; rr < 4; ++rr) {
            const int row = warp * 4 + rr;
            float s = psum[row * C4 + lane] + psum[row * C4 + lane + 32]
                    + psum[row * C4 + lane + 64] + psum[row * C4 + lane + 96];
#pragma unroll
            for (int off = 16; off; off >>= 1)
                s += __shfl_xor_sync(0xffffffffu, s, off);
            if (lane == 0) sdot[row] = s;
        }
    }
    __syncthreads();
    if (warp == 0) {
        float v0 = sdot[lane], v1 = sdot[lane + 32];
        float mn = fminf(v0, v1), mx = fmaxf(v0, v1);
#pragma unroll
        for (int off = 16; off; off >>= 1) {
            mn = fminf(mn, __shfl_xor_sync(0xffffffffu, mn, off));
            mx = fmaxf(mx, __shfl_xor_sync(0xffffffffu, mx, off));
        }
        if (lane == 0) {
            atomicMin(&g_mnk[b_own], enc(mn));
            atomicMax(&g_mxk[b_own], enc(mx));
        }
    }
    ARRIVE_LINE(&cnt7[b_own]);
    WAIT_LINES(&cnt7[b_own], 1, 16);

    if (t < 64) {
        const float mn = dec(g_mnk[b_own]);
        const float mx = dec(g_mxk[b_own]);
        const float z = ((sdot[t] - mn) / (mx - mn) - 0.65f) / 0.15f;
        out[b_own * HW + s_own * 64 + t] = 1.0f / (1.0f + __expf(-z));
    }

    // final ack + reset by block 0
    ARRIVE_LINE(&cnt8[g & 15]);
    if (g == 0 && t == 0) {
        unsigned s;
        do { s = 0;
#pragma unroll
             for (int i = 0; i < 16; ++i) s += ld_relaxed(&cnt8[i].v);
        } while (s < (unsigned)NBLK);
#pragma unroll
        for (int i = 0; i < 8;  ++i) { cnt0[i].v = 0u; cnt2[i].v = 0u;
                                       cnt3[i].v = 0u; cnt7[i].v = 0u; }
        cnt4[0].v = 0u; cnt4[1].v = 0u; cnt6[0].v = 0u;
#pragma unroll
        for (int i = 0; i < 16; ++i) cnt8[i].v = 0u;
#pragma unroll
        for (int b = 0; b < Bb; ++b) { g_mnk[b] = 0xFFFFFFFFu; g_mxk[b] = 0u; }
        __threadfence();
    }
}

// ---------------------------------------------------------------------------
extern "C" void kernel_launch(void* const* d_in, const int* in_sizes, int n_in,
                              void* d_out, int out_size) {
    const float* x      = (const float*)d_in[0];
    const float* conv_w = (const float*)d_in[1];
    const float* conv_b = (const float*)d_in[2];
    const float* q_w    = (const float*)d_in[3];
    // d_in[4] = q_b: per-batch constant, cancels in min/max normalization.
    const float* k_w    = (const float*)d_in[5];
    const float* k_b    = (const float*)d_in[6];
    float* out = (float*)d_out;

    cudaFuncSetAttribute(fused_kernel,
                         cudaFuncAttributeMaxDynamicSharedMemorySize,
                         DYN_BYTES);
    fused_kernel<<<NBLK, NTHR, DYN_BYTES>>>(x, conv_w, conv_b, q_w, k_w, k_b, out);
}

// round 7
// speedup vs baseline: 1.0011x; 1.0011x over previous
#include <cuda_runtime.h>

#define Bb   8
#define HW   1024
#define Cc   512
#define C4   128

// ---------------- scratch (__device__ globals; fully rewritten each launch) --
__device__ __align__(16) float g_partial[Bb][16][Cc];
__device__ __align__(16) float g_xsum[Bb][Cc];
__device__ __align__(16) float g_xr[Bb][Cc];
__device__ __align__(16) float g_ksum[Bb][Cc];
__device__ __align__(16) float g_wpart[16][Bb][Cc];
__device__ __align__(16) float g_w[Bb][Cc];
__device__ __align__(16) float g_upart[16][Bb][Cc];
__device__ float    g_dot[Bb][HW];
__device__ unsigned g_mnk[Bb];
__device__ unsigned g_mxk[Bb];

__device__ __forceinline__ unsigned enc(float f) {
    unsigned u = __float_as_uint(f);
    return (u & 0x80000000u) ? ~u : (u | 0x80000000u);
}
__device__ __forceinline__ float dec(unsigned k) {
    return (k & 0x80000000u) ? __uint_as_float(k ^ 0x80000000u)
                             : __uint_as_float(~k);
}

// ---------------- K1: column partial sums of x (also resets minmax atomics) --
__global__ void __launch_bounds__(512) k1_colsum(const float* __restrict__ x) {
    __shared__ __align__(16) float4 shP[4][C4];
    const int g = blockIdx.x, t = threadIdx.x;
    const int b = g >> 4, s = g & 15;
    const int c4 = t & 127, rs = t >> 7;

    if (g == 0 && t < Bb) { g_mnk[t] = 0xFFFFFFFFu; g_mxk[t] = 0u; }

    const float4* base = reinterpret_cast<const float4*>(x)
                       + ((size_t)(b * HW + s * 64 + rs * 16)) * C4 + c4;
    float4 acc = make_float4(0.f, 0.f, 0.f, 0.f);
#pragma unroll
    for (int p = 0; p < 16; ++p) {
        float4 v = base[(size_t)p * C4];
        acc.x += v.x; acc.y += v.y; acc.z += v.z; acc.w += v.w;
    }
    shP[rs][c4] = acc;
    __syncthreads();
    if (t < C4) {
        float4 a = shP[0][t], p1 = shP[1][t], p2 = shP[2][t], p3 = shP[3][t];
        a.x += p1.x + p2.x + p3.x;  a.y += p1.y + p2.y + p3.y;
        a.z += p1.z + p2.z + p3.z;  a.w += p1.w + p2.w + p3.w;
        reinterpret_cast<float4*>(g_partial[b][s])[t] = a;
    }
}

// ---------------- K2a: reduce partials -> Xsum. grid 8 (block = batch). ------
__global__ void __launch_bounds__(512) k2a_xsum() {
    const int b = blockIdx.x, t = threadIdx.x;
    float a = 0.f;
#pragma unroll
    for (int s = 0; s < 16; ++s) a += g_partial[b][s][t];
    g_xsum[b][t] = a;
}

// ---------------- generic 64-block batched matvec stage ----------------------
// out[b][o] = sum_c W[o][c]*in[b][c] + bias_scale*bias[o] + (add_in ? in[b][o] : 0)
template <bool ADD_IN>
__device__ __forceinline__ void matvec_stage(const float (*in)[Cc],
                                             const float* __restrict__ W,
                                             const float* __restrict__ bias,
                                             float (*outv)[Cc]) {
    __shared__ __align__(16) float shA[Bb][Cc];
    __shared__ float s_part[16][Bb];
    float4* shA4 = reinterpret_cast<float4*>(shA);
    const int a = blockIdx.x, t = threadIdx.x;
    const int warp = t >> 5, lane = t & 31;

#pragma unroll
    for (int i = 0; i < 2; ++i)
        shA4[t + i * 512] = reinterpret_cast<const float4*>(in)[t + i * 512];
    __syncthreads();

    const int rowL = warp >> 1, h = warp & 1;
    const int o = a * 8 + rowL;
    const float4* W4 = reinterpret_cast<const float4*>(W) + (size_t)o * C4;
    float acc[Bb];
#pragma unroll
    for (int b = 0; b < Bb; ++b) acc[b] = 0.f;
#pragma unroll
    for (int k = 0; k < 2; ++k) {
        const int c4 = h * 64 + k * 32 + lane;
        const float4 wv = W4[c4];
#pragma unroll
        for (int b = 0; b < Bb; ++b) {
            const float4 xa = shA4[b * C4 + c4];
            acc[b] += wv.x * xa.x + wv.y * xa.y + wv.z * xa.z + wv.w * xa.w;
        }
    }
#pragma unroll
    for (int b = 0; b < Bb; ++b)
#pragma unroll
        for (int off = 16; off; off >>= 1)
            acc[b] += __shfl_xor_sync(0xffffffffu, acc[b], off);
    if (lane == 0)
#pragma unroll
        for (int b = 0; b < Bb; ++b) s_part[warp][b] = acc[b];
    __syncthreads();
    if (t < 64) {
        const int rL = t >> 3, b = t & 7;
        const int oo = a * 8 + rL;
        float v = s_part[rL * 2][b] + s_part[rL * 2 + 1][b]
                + (float)HW * bias[oo];
        if (ADD_IN) v += shA[b][oo];
        outv[b][oo] = v;
    }
}

__global__ void __launch_bounds__(512)
k2b_xr(const float* __restrict__ conv_w, const float* __restrict__ conv_b) {
    matvec_stage<true>(g_xsum, conv_w, conv_b, g_xr);
}
__global__ void __launch_bounds__(512)
k3_ksum(const float* __restrict__ k_w, const float* __restrict__ k_b) {
    matvec_stage<false>(g_xr, k_w, k_b, g_ksum);
}

// ---------------- K4: v = KsumAll - Ksum; wpart[j] = q_w^T v over o-chunk ----
__global__ void __launch_bounds__(512) k4_wpart(const float* __restrict__ q_w) {
    __shared__ __align__(16) float shA[Bb][Cc];
    __shared__ float shB[Cc];
    float4* shA4 = reinterpret_cast<float4*>(shA);
    const int j = blockIdx.x, t = threadIdx.x;
    const int lane = t & 31;

#pragma unroll
    for (int i = 0; i < 2; ++i)
        shA4[t + i * 512] = reinterpret_cast<const float4*>(g_ksum)[t + i * 512];
    __syncthreads();
    float tot = 0.f;
#pragma unroll
    for (int b = 0; b < Bb; ++b) tot += shA[b][t];
    shB[t] = tot;
    __syncthreads();
#pragma unroll
    for (int b = 0; b < Bb; ++b) shA[b][t] = shB[t] - shA[b][t];   // v in place
    __syncthreads();

    float vreg[Bb];
#pragma unroll
    for (int b = 0; b < Bb; ++b) vreg[b] = shA[b][j * 32 + lane];
    float acc[Bb];
#pragma unroll
    for (int b = 0; b < Bb; ++b) acc[b] = 0.f;
#pragma unroll
    for (int oo = 0; oo < 32; ++oo) {
        const float wv = q_w[(size_t)(j * 32 + oo) * Cc + t];
#pragma unroll
        for (int b = 0; b < Bb; ++b)
            acc[b] += wv * __shfl_sync(0xffffffffu, vreg[b], oo);
    }
#pragma unroll
    for (int b = 0; b < Bb; ++b) g_wpart[j][b][t] = acc[b];
}

// ---------------- K4b: reduce wpart -> w. grid 8. ----------------------------
__global__ void __launch_bounds__(512) k4b_wred() {
    const int b = blockIdx.x, t = threadIdx.x;
    float a = 0.f;
#pragma unroll
    for (int jj = 0; jj < 16; ++jj) a += g_wpart[jj][b][t];
    g_w[b][t] = a;
}

// ---------------- K5: upart[j] = conv_w^T w over o-chunk ---------------------
__global__ void __launch_bounds__(512) k5_upart(const float* __restrict__ conv_w) {
    __shared__ float shW[Bb][32];
    const int j = blockIdx.x, t = threadIdx.x;
    const int lane = t & 31;

    if (t < 256) shW[t >> 5][t & 31] = g_w[t >> 5][j * 32 + (t & 31)];
    __syncthreads();

    float vreg[Bb];
#pragma unroll
    for (int b = 0; b < Bb; ++b) vreg[b] = shW[b][lane];
    float acc[Bb];
#pragma unroll
    for (int b = 0; b < Bb; ++b) acc[b] = 0.f;
#pragma unroll
    for (int oo = 0; oo < 32; ++oo) {
        const float wv = conv_w[(size_t)(j * 32 + oo) * Cc + t];
#pragma unroll
        for (int b = 0; b < Bb; ++b)
            acc[b] += wv * __shfl_sync(0xffffffffu, vreg[b], oo);
    }
#pragma unroll
    for (int b = 0; b < Bb; ++b) g_upart[j][b][t] = acc[b];
}

// ---------------- K6: u assemble + dot + per-batch minmax atomics ------------
__global__ void __launch_bounds__(512) k6_dot(const float* __restrict__ x) {
    __shared__ float psum[64][C4];      // 32 KB
    __shared__ float shB[Cc];
    __shared__ float sdot[64];
    const int g = blockIdx.x, t = threadIdx.x;
    const int b = g >> 4, s = g & 15;
    const int warp = t >> 5, lane = t & 31;
    const int c4 = t & 127, rs = t >> 7;

    // u[t] = w[b][t] + sum_j upart[j][b][t]
    {
        float a = g_w[b][t];
#pragma unroll
        for (int jj = 0; jj < 16; ++jj) a += g_upart[jj][b][t];
        shB[t] = a;
    }
    __syncthreads();

    const float4 uv = reinterpret_cast<const float4*>(shB)[c4];
    const float4* base = reinterpret_cast<const float4*>(x)
                       + ((size_t)(b * HW + s * 64 + rs * 16)) * C4 + c4;
#pragma unroll
    for (int p = 0; p < 16; ++p) {
        const float4 xv = base[(size_t)p * C4];
        psum[rs * 16 + p][c4] = xv.x * uv.x + xv.y * uv.y + xv.z * uv.z + xv.w * uv.w;
    }
    __syncthreads();

#pragma unroll
    for (int rr = 0; rr < 4; ++rr) {
        const int row = warp * 4 + rr;
        float sm = psum[row][lane] + psum[row][lane + 32]
                 + psum[row][lane + 64] + psum[row][lane + 96];
#pragma unroll
        for (int off = 16; off; off >>= 1)
            sm += __shfl_xor_sync(0xffffffffu, sm, off);
        if (lane == 0) { sdot[row] = sm; g_dot[b][s * 64 + row] = sm; }
    }
    __syncthreads();
    if (warp == 0) {
        float v0 = sdot[lane], v1 = sdot[lane + 32];
        float mn = fminf(v0, v1), mx = fmaxf(v0, v1);
#pragma unroll
        for (int off = 16; off; off >>= 1) {
            mn = fminf(mn, __shfl_xor_sync(0xffffffffu, mn, off));
            mx = fmaxf(mx, __shfl_xor_sync(0xffffffffu, mx, off));
        }
        if (lane == 0) {
            atomicMin(&g_mnk[b], enc(mn));
            atomicMax(&g_mxk[b], enc(mx));
        }
    }
}

// ---------------- K7: normalize + sigmoid -> out. grid 8 x 1024. -------------
__global__ void __launch_bounds__(1024) k7_out(float* __restrict__ out) {
    const int b = blockIdx.x, i = threadIdx.x;
    const float mn = dec(g_mnk[b]);
    const float mx = dec(g_mxk[b]);
    const float z = ((g_dot[b][i] - mn) / (mx - mn) - 0.65f) / 0.15f;
    out[b * HW + i] = 1.0f / (1.0f + __expf(-z));
}

// ---------------------------------------------------------------------------
extern "C" void kernel_launch(void* const* d_in, const int* in_sizes, int n_in,
                              void* d_out, int out_size) {
    const float* x      = (const float*)d_in[0];
    const float* conv_w = (const float*)d_in[1];
    const float* conv_b = (const float*)d_in[2];
    const float* q_w    = (const float*)d_in[3];
    // d_in[4] = q_b: per-batch constant, cancels in min/max normalization.
    const float* k_w    = (const float*)d_in[5];
    const float* k_b    = (const float*)d_in[6];
    float* out = (float*)d_out;

    k1_colsum<<<128, 512>>>(x);
    k2a_xsum <<<  8, 512>>>();
    k2b_xr   <<< 64, 512>>>(conv_w, conv_b);
    k3_ksum  <<< 64, 512>>>(k_w, k_b);
    k4_wpart <<< 16, 512>>>(q_w);
    k4b_wred <<<  8, 512>>>();
    k5_upart <<< 16, 512>>>(conv_w);
    k6_dot   <<<128, 512>>>(x);
    k7_out   <<<  8, 1024>>>(out);
}